// round 1
// baseline (speedup 1.0000x reference)
#include <cuda_runtime.h>

#define RES 2048
#define NPTS 4194304

__global__ void __launch_bounds__(256) bilerp_kernel(
    const float* __restrict__ pts,      // [N,2]
    const float* __restrict__ grid,     // [R,R,3]
    float* __restrict__ out,            // [N,3]
    int n)
{
    int i = blockIdx.x * blockDim.x + threadIdx.x;
    if (i >= n) return;

    // coalesced float2 load of the point
    float2 p = reinterpret_cast<const float2*>(pts)[i];

    const float scale = (float)(RES - 1);
    float sx = p.x * scale;
    float sy = p.y * scale;

    int xl = (int)floorf(sx);
    int yl = (int)floorf(sy);
    xl = min(max(xl, 0), RES - 2);
    yl = min(max(yl, 0), RES - 2);

    float tx = sx - (float)xl;
    float ty = sy - (float)yl;

    // feature_params[y, x, c] -> ((y*RES + x)*3 + c)
    const float* row0 = grid + ((size_t)yl * RES + xl) * 3;         // c00|c01 : 6 contiguous floats
    const float* row1 = grid + ((size_t)(yl + 1) * RES + xl) * 3;   // c10|c11 : 6 contiguous floats

    float c00_0 = __ldg(row0 + 0), c00_1 = __ldg(row0 + 1), c00_2 = __ldg(row0 + 2);
    float c01_0 = __ldg(row0 + 3), c01_1 = __ldg(row0 + 4), c01_2 = __ldg(row0 + 5);
    float c10_0 = __ldg(row1 + 0), c10_1 = __ldg(row1 + 1), c10_2 = __ldg(row1 + 2);
    float c11_0 = __ldg(row1 + 3), c11_1 = __ldg(row1 + 4), c11_2 = __ldg(row1 + 5);

    // lerp along x:  c0 = c00 + tx*(c01-c00)  == c00*(1-tx) + c01*tx  (fp32-equivalent form)
    float omtx = 1.0f - tx;
    float omty = 1.0f - ty;

    float c0_0 = c00_0 * omtx + c01_0 * tx;
    float c0_1 = c00_1 * omtx + c01_1 * tx;
    float c0_2 = c00_2 * omtx + c01_2 * tx;
    float c1_0 = c10_0 * omtx + c11_0 * tx;
    float c1_1 = c10_1 * omtx + c11_1 * tx;
    float c1_2 = c10_2 * omtx + c11_2 * tx;

    float r0 = c0_0 * omty + c1_0 * ty;
    float r1 = c0_1 * omty + c1_1 * ty;
    float r2 = c0_2 * omty + c1_2 * ty;

    // coalesced-ish: warp writes 384 contiguous bytes
    float* o = out + (size_t)i * 3;
    o[0] = r0;
    o[1] = r1;
    o[2] = r2;
}

extern "C" void kernel_launch(void* const* d_in, const int* in_sizes, int n_in,
                              void* d_out, int out_size)
{
    const float* pts  = (const float*)d_in[0];   // input  [N,2]
    const float* grid = (const float*)d_in[1];   // feature_params [R,R,3]
    float* out = (float*)d_out;

    int n = in_sizes[0] / 2;   // N points
    int threads = 256;
    int blocks = (n + threads - 1) / threads;
    bilerp_kernel<<<blocks, threads>>>(pts, grid, out, n);
}

// round 2
// speedup vs baseline: 1.2333x; 1.2333x over previous
#include <cuda_runtime.h>

#define RES 2048

__global__ void __launch_bounds__(256) bilerp_kernel(
    const float*  __restrict__ pts,   // [N,2]
    const float4* __restrict__ grid4, // [R,R,3] viewed as float4
    float* __restrict__ out,          // [N,3]
    int n)
{
    int i = blockIdx.x * blockDim.x + threadIdx.x;
    if (i >= n) return;

    float2 p = reinterpret_cast<const float2*>(pts)[i];

    const float scale = (float)(RES - 1);
    float sx = p.x * scale;
    float sy = p.y * scale;

    int xl = (int)floorf(sx);
    int yl = (int)floorf(sy);
    xl = min(max(xl, 0), RES - 2);
    yl = min(max(yl, 0), RES - 2);

    float tx = sx - (float)xl;
    float ty = sy - (float)yl;
    float omtx = 1.0f - tx;
    float omty = 1.0f - ty;

    // word index of the first float of row0's 6-float segment
    int w   = (yl * RES + xl) * 3;
    int off = w & 3;                       // same for row1: row stride = 6144 words (div by 4)
    const float4* base0 = grid4 + (w >> 2);
    const float4* base1 = base0 + (RES * 3 / 4);   // +1536 float4s = one grid row

    float4 a0 = __ldg(base0);
    float4 a1 = __ldg(base0 + 1);
    float4 b0 = __ldg(base1);
    float4 b1 = __ldg(base1 + 1);
    float4 a2 = make_float4(0.f, 0.f, 0.f, 0.f);
    float4 b2 = a2;
    if (off == 3) {
        a2 = __ldg(base0 + 2);
        b2 = __ldg(base1 + 2);
    }

    // x-lerp both rows; s[k] = word[off + k] of each segment
    float c0_0, c0_1, c0_2, c1_0, c1_1, c1_2;
    switch (off) {
    case 0:
        c0_0 = a0.x * omtx + a0.w * tx;
        c0_1 = a0.y * omtx + a1.x * tx;
        c0_2 = a0.z * omtx + a1.y * tx;
        c1_0 = b0.x * omtx + b0.w * tx;
        c1_1 = b0.y * omtx + b1.x * tx;
        c1_2 = b0.z * omtx + b1.y * tx;
        break;
    case 1:
        c0_0 = a0.y * omtx + a1.x * tx;
        c0_1 = a0.z * omtx + a1.y * tx;
        c0_2 = a0.w * omtx + a1.z * tx;
        c1_0 = b0.y * omtx + b1.x * tx;
        c1_1 = b0.z * omtx + b1.y * tx;
        c1_2 = b0.w * omtx + b1.z * tx;
        break;
    case 2:
        c0_0 = a0.z * omtx + a1.y * tx;
        c0_1 = a0.w * omtx + a1.z * tx;
        c0_2 = a1.x * omtx + a1.w * tx;
        c1_0 = b0.z * omtx + b1.y * tx;
        c1_1 = b0.w * omtx + b1.z * tx;
        c1_2 = b1.x * omtx + b1.w * tx;
        break;
    default: // 3
        c0_0 = a0.w * omtx + a1.z * tx;
        c0_1 = a1.x * omtx + a1.w * tx;
        c0_2 = a1.y * omtx + a2.x * tx;
        c1_0 = b0.w * omtx + b1.z * tx;
        c1_1 = b1.x * omtx + b1.w * tx;
        c1_2 = b1.y * omtx + b2.x * tx;
        break;
    }

    float r0 = c0_0 * omty + c1_0 * ty;
    float r1 = c0_1 * omty + c1_1 * ty;
    float r2 = c0_2 * omty + c1_2 * ty;

    float* o = out + (size_t)i * 3;
    o[0] = r0;
    o[1] = r1;
    o[2] = r2;
}

extern "C" void kernel_launch(void* const* d_in, const int* in_sizes, int n_in,
                              void* d_out, int out_size)
{
    const float*  pts  = (const float*)d_in[0];
    const float4* grid = (const float4*)d_in[1];
    float* out = (float*)d_out;

    int n = in_sizes[0] / 2;
    int threads = 256;
    int blocks = (n + threads - 1) / threads;
    bilerp_kernel<<<blocks, threads>>>(pts, grid, out, n);
}